// round 6
// baseline (speedup 1.0000x reference)
#include <cuda_runtime.h>
#include <math.h>

#define RIR_LENGTH 3968
#define PAD        40
#define BATCH      128
#define MAXO       15
#define GRID_N     31
#define GRID_TOT   (31*31*31)    // 29791
#define NIMG       4991          // |x|+|y|+|z| <= 15 lattice points
#define FSR        46.64723032f  // fp32(16000/343)
#define INV_PI     0.3183098862f

#define NBUCK      126           // buckets of 32 delay-bins, di in [0, 4007]
#define MAXENT     5120
#define WMAX       64
#define DIMAX      4007          // di <= 4007 <=> t0 <= 3967

__device__ int    g_xyz[NIMG + 8];
__device__ int    g_cnt;
__device__ float4 g_ent[BATCH * MAXENT];
__device__ int    g_boff[BATCH][NBUCK + 1];
__device__ float4 g_wrap[BATCH * WMAX * 2];
__device__ int    g_wcnt[BATCH];

// ---------------------------------------------------------------------------
__global__ void k_reset() {
    int t = threadIdx.x;
    if (t == 0) g_cnt = 0;
    if (t < BATCH) g_wcnt[t] = 0;
}

__global__ void k_build_xyz() {
    int idx = blockIdx.x * blockDim.x + threadIdx.x;
    if (idx >= GRID_TOT) return;
    int ix = idx % GRID_N - MAXO;
    int iy = (idx / GRID_N) % GRID_N - MAXO;
    int iz = idx / (GRID_N * GRID_N) - MAXO;
    if (abs(ix) + abs(iy) + abs(iz) <= MAXO) {
        int p = atomicAdd(&g_cnt, 1);
        if (p < NIMG)
            g_xyz[p] = (ix + 16) | ((iy + 16) << 8) | ((iz + 16) << 16);
    }
}

// Zero the rir region of d_out and compute toa.
__global__ void k_init(const float* __restrict__ inp, float* __restrict__ out) {
    int i = blockIdx.x * blockDim.x + threadIdx.x;
    int total = BATCH * RIR_LENGTH;
    for (int j = i; j < total; j += gridDim.x * blockDim.x) out[j] = 0.0f;
    if (i < BATCH) {
        const float* r = inp + i * 12;
        float dx = __fsub_rn(__fmul_rn(r[3], r[0]), __fmul_rn(r[6], r[0]));
        float dy = __fsub_rn(__fmul_rn(r[4], r[1]), __fmul_rn(r[7], r[1]));
        float dz = __fsub_rn(__fmul_rn(r[5], r[2]), __fmul_rn(r[8], r[2]));
        float ss = __fadd_rn(__fadd_rn(__fmul_rn(dx, dx), __fmul_rn(dy, dy)),
                             __fmul_rn(dz, dz));
        float dist = __fsqrt_rn(ss);
        out[total + i] = __fadd_rn((float)PAD, __fmul_rn(dist, FSR));
    }
}

// ---------------------------------------------------------------------------
// Build pass: per-batch counting sort of image entries by delay bucket.
// Entry = {delay, A2, cos(pi*delay/40), sin(pi*delay/40)}.
#define BTPB 256
__global__ __launch_bounds__(BTPB) void k_build(const float* __restrict__ inp,
                                                float* __restrict__ out) {
    __shared__ float sPW[16], sPL[9], sPH[9], sGeo[9];
    __shared__ int hist[NBUCK], base[NBUCK + 1], cur[NBUCK];

    const int b   = blockIdx.x;
    const int tid = threadIdx.x;

    for (int k = tid; k < NBUCK; k += BTPB) hist[k] = 0;

    if (tid == 0) {
        const float* r = inp + b * 12;
        float rx = r[0], ry = r[1], rz = r[2];
        sGeo[0] = rx;                  sGeo[1] = ry;                  sGeo[2] = rz;
        sGeo[3] = __fmul_rn(r[3], rx); sGeo[4] = __fmul_rn(r[4], ry); sGeo[5] = __fmul_rn(r[5], rz);
        sGeo[6] = __fmul_rn(r[6], rx); sGeo[7] = __fmul_rn(r[7], ry); sGeo[8] = __fmul_rn(r[8], rz);
        float aw  = __fadd_rn(__fmul_rn(r[9],  0.84f), 0.01f);
        float a4  = __fadd_rn(__fmul_rn(r[10], 0.84f), 0.01f);
        float a5  = __fadd_rn(__fmul_rn(r[11], 0.84f), 0.01f);
        double trw = sqrt(1.0 - (double)aw);
        double tr4 = sqrt(1.0 - (double)a4);
        double tr5 = sqrt(1.0 - (double)a5);
        double p = 1.0;
        for (int e = 0; e < 16; e++) { sPW[e] = (float)p; p *= trw; }
        p = 1.0;
        for (int e = 0; e < 9;  e++) { sPL[e] = (float)p; p *= tr4; }
        p = 1.0;
        for (int e = 0; e < 9;  e++) { sPH[e] = (float)p; p *= tr5; }
    }
    __syncthreads();

    const float d0 = sGeo[0], d1 = sGeo[1], d2 = sGeo[2];
    const float m0 = sGeo[3], m1 = sGeo[4], m2 = sGeo[5];
    const float s0 = sGeo[6], s1 = sGeo[7], s2v = sGeo[8];

    // ---- phase 1: histogram ----
    for (int i = tid; i < NIMG; i += BTPB) {
        int pk = g_xyz[i];
        int ix = (pk & 255) - 16;
        int iy = ((pk >> 8) & 255) - 16;
        int iz = (pk >> 16) - 16;
        float img0 = (ix & 1) ? __fsub_rn(__fmul_rn(d0, (float)(ix + 1)), s0)
                              : __fadd_rn(__fmul_rn(d0, (float)ix), s0);
        float img1 = (iy & 1) ? __fsub_rn(__fmul_rn(d1, (float)(iy + 1)), s1)
                              : __fadd_rn(__fmul_rn(d1, (float)iy), s1);
        float img2 = (iz & 1) ? __fsub_rn(__fmul_rn(d2, (float)(iz + 1)), s2v)
                              : __fadd_rn(__fmul_rn(d2, (float)iz), s2v);
        float e0 = __fsub_rn(img0, m0);
        float e1 = __fsub_rn(img1, m1);
        float e2 = __fsub_rn(img2, m2);
        float ssq = __fadd_rn(__fadd_rn(__fmul_rn(e0, e0), __fmul_rn(e1, e1)),
                              __fmul_rn(e2, e2));
        float delay = __fmul_rn(__fsqrt_rn(ssq), FSR);
        float dif   = ceilf(delay);
        int   di    = (int)dif;
        float frac  = __fsub_rn(dif, delay);
        if (di <= DIMAX && frac != 0.0f)
            atomicAdd(&hist[di >> 5], 1);
    }
    __syncthreads();

    if (tid == 0) {
        int run = 0;
        for (int k = 0; k < NBUCK; k++) { base[k] = run; run += hist[k]; }
        base[NBUCK] = run;
    }
    __syncthreads();
    for (int k = tid; k < NBUCK; k += BTPB) cur[k] = base[k];
    for (int k = tid; k <= NBUCK; k += BTPB) g_boff[b][k] = base[k];
    __syncthreads();

    // ---- phase 2: place entries ----
    float4* slab = g_ent + b * MAXENT;
    for (int i = tid; i < NIMG; i += BTPB) {
        int pk = g_xyz[i];
        int ix = (pk & 255) - 16;
        int iy = ((pk >> 8) & 255) - 16;
        int iz = (pk >> 16) - 16;
        float img0 = (ix & 1) ? __fsub_rn(__fmul_rn(d0, (float)(ix + 1)), s0)
                              : __fadd_rn(__fmul_rn(d0, (float)ix), s0);
        float img1 = (iy & 1) ? __fsub_rn(__fmul_rn(d1, (float)(iy + 1)), s1)
                              : __fadd_rn(__fmul_rn(d1, (float)iy), s1);
        float img2 = (iz & 1) ? __fsub_rn(__fmul_rn(d2, (float)(iz + 1)), s2v)
                              : __fadd_rn(__fmul_rn(d2, (float)iz), s2v);
        float e0 = __fsub_rn(img0, m0);
        float e1 = __fsub_rn(img1, m1);
        float e2 = __fsub_rn(img2, m2);
        float ssq = __fadd_rn(__fadd_rn(__fmul_rn(e0, e0), __fmul_rn(e1, e1)),
                              __fmul_rn(e2, e2));
        float dist  = __fsqrt_rn(ssq);
        float delay = __fmul_rn(dist, FSR);
        float dif   = ceilf(delay);
        int   di    = (int)dif;
        if (di > DIMAX) continue;
        float frac = __fsub_rn(dif, delay);

        int axy  = abs(ix) + abs(iy);
        int elo2 = (iz >= 0) ? (iz >> 1)       : ((-iz + 1) >> 1);
        int ehi2 = (iz >= 0) ? ((iz + 1) >> 1) : ((-iz) >> 1);
        float att = sPW[axy] * sPL[elo2] * sPH[ehi2];
        float amp = __fdiv_rn(att, dist);

        if (frac == 0.0f) {                      // pure spike: sinc peak only
            if (di < RIR_LENGTH) atomicAdd(&out[b * RIR_LENGTH + di], amp);
            continue;
        }

        float a2 = 0.5f * INV_PI * amp * sinpif(frac);
        if (di & 1) a2 = -a2;                    // (-1)^di
        int dm = di % 80;
        float cD, sD;
        sincospif(((float)dm - frac) * 0.025f, &sD, &cD);

        int slot = atomicAdd(&cur[di >> 5], 1);
        if (slot < MAXENT)
            slab[slot] = make_float4(delay, a2, cD, sD);

        if (di < PAD) {                          // near-field: JAX wrap duplicate
            int w = atomicAdd(&g_wcnt[b], 1);
            if (w < WMAX) {
                int dm2 = (dm + 48) % 80;        // (di+3968) % 80
                float cW, sW;
                sincospif(((float)dm2 - frac) * 0.025f, &sW, &cW);
                g_wrap[(b * WMAX + w) * 2 + 0] =
                    make_float4((float)(di + RIR_LENGTH), frac, a2, 0.f);
                g_wrap[(b * WMAX + w) * 2 + 1] = make_float4(cW, sW, 0.f, 0.f);
            }
        }
    }
}

// ---------------------------------------------------------------------------
// Gather pass: one thread per output bin.
__global__ __launch_bounds__(256) void k_gather(float* __restrict__ out) {
    const int b = blockIdx.y;
    const int j = blockIdx.x * 256 + threadIdx.x;
    const int wbase = j & ~31;
    const bool act = (j < RIR_LENGTH);           // uniform per warp (3968 = 124*32)

    const float jf = (float)j;
    const int jm = j % 80;
    float cj, sj;
    sincospif((float)jm * 0.025f, &sj, &cj);
    const float onej = (jm & 1) ? -1.f : 1.f;    // (-1)^j
    const float cjs = onej * cj;
    const float sjs = onej * sj;

    int lob = (wbase - 39) >> 5; if (lob < 0) lob = 0;
    int hib = (wbase + 71) >> 5; if (hib > NBUCK - 1) hib = NBUCK - 1;
    int e_lo = g_boff[b][lob];
    int e_hi = g_boff[b][hib + 1];
    if (!act) e_hi = e_lo;

    const float4* __restrict__ ent = g_ent + b * MAXENT;
    float a0 = 0.f, a1 = 0.f, a2 = 0.f, a3 = 0.f;

    int e = e_lo;
    for (; e + 4 <= e_hi; e += 4) {
        float4 E0 = ent[e], E1 = ent[e + 1], E2 = ent[e + 2], E3 = ent[e + 3];
        {
            float x = jf - E0.x;                 // exact
            if (fabsf(x) < 40.f) {
                float t = fmaf(cjs, E0.z, onej);
                t = fmaf(sjs, E0.w, t);
                a0 = fmaf(E0.y * t, __fdividef(1.f, x), a0);
            }
        }
        {
            float x = jf - E1.x;
            if (fabsf(x) < 40.f) {
                float t = fmaf(cjs, E1.z, onej);
                t = fmaf(sjs, E1.w, t);
                a1 = fmaf(E1.y * t, __fdividef(1.f, x), a1);
            }
        }
        {
            float x = jf - E2.x;
            if (fabsf(x) < 40.f) {
                float t = fmaf(cjs, E2.z, onej);
                t = fmaf(sjs, E2.w, t);
                a2 = fmaf(E2.y * t, __fdividef(1.f, x), a2);
            }
        }
        {
            float x = jf - E3.x;
            if (fabsf(x) < 40.f) {
                float t = fmaf(cjs, E3.z, onej);
                t = fmaf(sjs, E3.w, t);
                a3 = fmaf(E3.y * t, __fdividef(1.f, x), a3);
            }
        }
    }
    for (; e < e_hi; e++) {
        float4 E0 = ent[e];
        float x = jf - E0.x;
        if (fabsf(x) < 40.f) {
            float t = fmaf(cjs, E0.z, onej);
            t = fmaf(sjs, E0.w, t);
            a0 = fmaf(E0.y * t, __fdividef(1.f, x), a0);
        }
    }
    float acc = (a0 + a1) + (a2 + a3);

    // wrapped near-field taps land only in bins [3928, 3967]
    if (act && wbase + 31 >= RIR_LENGTH - PAD) {
        int wc = g_wcnt[b]; if (wc > WMAX) wc = WMAX;
        const float4* wp = g_wrap + b * WMAX * 2;
        for (int w = 0; w < wc; w++) {
            float4 A = wp[2 * w], B = wp[2 * w + 1];
            float x = (jf - A.x) + A.y;          // exact: int diff + frac
            if (fabsf(x) < 40.f) {
                float t = fmaf(cjs, B.x, onej);
                t = fmaf(sjs, B.y, t);
                acc = fmaf(A.z * t, __fdividef(1.f, x), acc);
            }
        }
    }

    if (act) {
        float* o = out + b * RIR_LENGTH + j;
        *o = *o + acc;                           // adds onto spikes
    }
}

// ---------------------------------------------------------------------------
extern "C" void kernel_launch(void* const* d_in, const int* in_sizes, int n_in,
                              void* d_out, int out_size) {
    const float* inp = (const float*)d_in[0];
    float* out = (float*)d_out;

    k_reset<<<1, 128>>>();
    k_build_xyz<<<(GRID_TOT + 255) / 256, 256>>>();
    k_init<<<512, 256>>>(inp, out);
    k_build<<<BATCH, BTPB>>>(inp, out);
    k_gather<<<dim3(16, BATCH), 256>>>(out);
}

// round 7
// speedup vs baseline: 1.4706x; 1.4706x over previous
#include <cuda_runtime.h>
#include <math.h>

#define RIR_LENGTH 3968
#define PAD        40
#define BATCH      128
#define MAXO       15
#define GRID_N     31
#define GRID_TOT   29791
#define FSR        46.64723032f  // fp32(16000/343)
#define INV_PI     0.3183098862f

#define DIMAX      4007          // di <= 4007 <=> lowest tap bin <= 3967
#define BSH        4             // bucket = 16 delay-bins
#define NBUCK      251           // ceil(4008/16)
#define MAXE       4992
#define WMAX       64
#define SPMAX      32
#define TPB        1024
#define AITER      ((GRID_TOT + TPB - 1) / TPB)   // 30

__global__ __launch_bounds__(TPB) void k_all(const float* __restrict__ inp,
                                             float* __restrict__ out) {
    extern __shared__ __align__(16) char dynsm[];
    float4* sEnt   = (float4*)dynsm;                         // [MAXE]
    float2* sCache = (float2*)(dynsm + MAXE * sizeof(float4));  // [MAXE]

    __shared__ float  sPW[16], sPL[9], sPH[9], sGeo[9];
    __shared__ int    hist[NBUCK], base[NBUCK + 1], cur[NBUCK];
    __shared__ int    s_icnt, s_nsp, s_nwr;
    __shared__ int    s_spk_i[SPMAX];
    __shared__ float  s_spk_a[SPMAX];
    __shared__ float4 s_wrap[WMAX * 2];

    const int b    = blockIdx.x;
    const int tid  = threadIdx.x;
    const int lane = tid & 31;

    for (int k = tid; k < NBUCK; k += TPB) hist[k] = 0;
    if (tid == 0) {
        s_icnt = 0; s_nsp = 0; s_nwr = 0;
        const float* r = inp + b * 12;
        float rx = r[0], ry = r[1], rz = r[2];
        sGeo[0] = rx;                  sGeo[1] = ry;                  sGeo[2] = rz;
        sGeo[3] = __fmul_rn(r[3], rx); sGeo[4] = __fmul_rn(r[4], ry); sGeo[5] = __fmul_rn(r[5], rz);
        sGeo[6] = __fmul_rn(r[6], rx); sGeo[7] = __fmul_rn(r[7], ry); sGeo[8] = __fmul_rn(r[8], rz);
        float aw  = __fadd_rn(__fmul_rn(r[9],  0.84f), 0.01f);
        float a4  = __fadd_rn(__fmul_rn(r[10], 0.84f), 0.01f);
        float a5  = __fadd_rn(__fmul_rn(r[11], 0.84f), 0.01f);
        double trw = sqrt(1.0 - (double)aw);
        double tr4 = sqrt(1.0 - (double)a4);
        double tr5 = sqrt(1.0 - (double)a5);
        double p = 1.0;
        for (int e = 0; e < 16; e++) { sPW[e] = (float)p; p *= trw; }
        p = 1.0;
        for (int e = 0; e < 9;  e++) { sPL[e] = (float)p; p *= tr4; }
        p = 1.0;
        for (int e = 0; e < 9;  e++) { sPH[e] = (float)p; p *= tr5; }
        // toa
        float dx = __fsub_rn(__fmul_rn(r[3], rx), __fmul_rn(r[6], rx));
        float dy = __fsub_rn(__fmul_rn(r[4], ry), __fmul_rn(r[7], ry));
        float dz = __fsub_rn(__fmul_rn(r[5], rz), __fmul_rn(r[8], rz));
        float ssq = __fadd_rn(__fadd_rn(__fmul_rn(dx, dx), __fmul_rn(dy, dy)),
                              __fmul_rn(dz, dz));
        out[BATCH * RIR_LENGTH + b] =
            __fadd_rn((float)PAD, __fmul_rn(__fsqrt_rn(ssq), FSR));
    }
    __syncthreads();

    const float d0 = sGeo[0], d1 = sGeo[1], d2 = sGeo[2];
    const float m0 = sGeo[3], m1 = sGeo[4], m2 = sGeo[5];
    const float s0 = sGeo[6], s1 = sGeo[7], s2v = sGeo[8];

    // ---- phase A: grid scan, histogram + warp-aggregated compaction ----
    for (int it = 0; it < AITER; it++) {
        int idx = it * TPB + tid;
        bool live = false;
        float delay = 0.f, amp = 0.f;
        if (idx < GRID_TOT) {
            int iz  = idx / 961;
            int rem = idx - iz * 961;
            int iy  = rem / 31;
            int ix  = rem - iy * 31;
            ix -= MAXO; iy -= MAXO; iz -= MAXO;
            int axy = abs(ix) + abs(iy);
            if (axy + abs(iz) <= MAXO) {
                float img0 = (ix & 1) ? __fsub_rn(__fmul_rn(d0, (float)(ix + 1)), s0)
                                      : __fadd_rn(__fmul_rn(d0, (float)ix), s0);
                float img1 = (iy & 1) ? __fsub_rn(__fmul_rn(d1, (float)(iy + 1)), s1)
                                      : __fadd_rn(__fmul_rn(d1, (float)iy), s1);
                float img2 = (iz & 1) ? __fsub_rn(__fmul_rn(d2, (float)(iz + 1)), s2v)
                                      : __fadd_rn(__fmul_rn(d2, (float)iz), s2v);
                float e0 = __fsub_rn(img0, m0);
                float e1 = __fsub_rn(img1, m1);
                float e2 = __fsub_rn(img2, m2);
                float ssq = __fadd_rn(__fadd_rn(__fmul_rn(e0, e0), __fmul_rn(e1, e1)),
                                      __fmul_rn(e2, e2));
                float dist = __fsqrt_rn(ssq);
                delay = __fmul_rn(dist, FSR);
                float dif = ceilf(delay);
                int   di  = (int)dif;
                if (di <= DIMAX) {
                    live = true;
                    int elo2 = (iz >= 0) ? (iz >> 1)       : ((-iz + 1) >> 1);
                    int ehi2 = (iz >= 0) ? ((iz + 1) >> 1) : ((-iz) >> 1);
                    float att = sPW[axy] * sPL[elo2] * sPH[ehi2];
                    amp = __fdiv_rn(att, dist);
                    if (__fsub_rn(dif, delay) != 0.0f)
                        atomicAdd(&hist[di >> BSH], 1);
                }
            }
        }
        unsigned msk = __ballot_sync(0xffffffffu, live);
        if (msk) {
            int cnt = __popc(msk);
            int ldr = __ffs(msk) - 1;
            int bp  = 0;
            if (lane == ldr) bp = atomicAdd(&s_icnt, cnt);
            bp = __shfl_sync(0xffffffffu, bp, ldr);
            if (live) {
                int rk = __popc(msk & ((1u << lane) - 1u));
                sCache[bp + rk] = make_float2(delay, amp);
            }
        }
    }
    __syncthreads();

    // ---- prefix scan (serial, small) ----
    if (tid == 0) {
        int run = 0;
        for (int k = 0; k < NBUCK; k++) { base[k] = run; run += hist[k]; }
        base[NBUCK] = run;
    }
    __syncthreads();
    for (int k = tid; k < NBUCK; k += TPB) cur[k] = base[k];
    __syncthreads();

    // ---- phase B: finalize entries ----
    int n_img = s_icnt;
    for (int c = tid; c < n_img; c += TPB) {
        float2 E = sCache[c];
        float delay = E.x, amp = E.y;
        float dif = ceilf(delay);
        int   di  = (int)dif;
        float frac = __fsub_rn(dif, delay);
        if (frac == 0.0f) {                       // spike: sinc peak only
            if (di < RIR_LENGTH) {
                int sp = atomicAdd(&s_nsp, 1);
                if (sp < SPMAX) { s_spk_i[sp] = di; s_spk_a[sp] = amp; }
            }
            continue;
        }
        float a2 = 0.5f * INV_PI * amp * sinpif(frac);
        if (di & 1) a2 = -a2;                     // (-1)^di
        int dm = di % 80;
        float cD, sD;
        sincospif(((float)dm - frac) * 0.025f, &sD, &cD);
        int slot = atomicAdd(&cur[di >> BSH], 1);
        sEnt[slot] = make_float4(delay, a2, cD, sD);
        if (di < PAD) {                           // near-field: JAX wrap duplicate
            int w = atomicAdd(&s_nwr, 1);
            if (w < WMAX) {
                int dm2 = (dm + 48) % 80;         // (di + 3968) % 80
                float cW, sW;
                sincospif(((float)dm2 - frac) * 0.025f, &sW, &cW);
                s_wrap[2 * w + 0] = make_float4((float)(di + RIR_LENGTH), frac, a2, 0.f);
                s_wrap[2 * w + 1] = make_float4(cW, sW, 0.f, 0.f);
            }
        }
    }
    __syncthreads();

    // ---- phase D: gather, 32 consecutive bins per warp ----
    int nsp = min(s_nsp, SPMAX);
    int nwr = min(s_nwr, WMAX);
    float* orir = out + b * RIR_LENGTH;

    #pragma unroll
    for (int m = 0; m < 4; m++) {
        int j      = m * TPB + tid;
        int wstart = m * TPB + (tid & ~31);
        bool act   = (j < RIR_LENGTH);            // warp-uniform (3968 % 32 == 0)

        float jf = (float)j;
        int jm = j % 80;
        float cj, sj;
        sincospif((float)jm * 0.025f, &sj, &cj);
        float onej = (jm & 1) ? -1.f : 1.f;
        float cjs = onej * cj;
        float sjs = onej * sj;

        int lob = (wstart - 39) >> BSH; if (lob < 0) lob = 0;
        int hib = (wstart + 71) >> BSH; if (hib > NBUCK - 1) hib = NBUCK - 1;
        int e_lo = base[lob];
        int e_hi = act ? base[hib + 1] : e_lo;

        float a0 = 0.f, a1 = 0.f, a2v = 0.f, a3 = 0.f;
        int e = e_lo;
        for (; e + 4 <= e_hi; e += 4) {
            float4 E0 = sEnt[e], E1 = sEnt[e + 1], E2 = sEnt[e + 2], E3 = sEnt[e + 3];
            {
                float x = jf - E0.x;
                if (fabsf(x) < 40.f) {
                    float t = fmaf(cjs, E0.z, onej);
                    t = fmaf(sjs, E0.w, t);
                    a0 = fmaf(E0.y * t, __fdividef(1.f, x), a0);
                }
            }
            {
                float x = jf - E1.x;
                if (fabsf(x) < 40.f) {
                    float t = fmaf(cjs, E1.z, onej);
                    t = fmaf(sjs, E1.w, t);
                    a1 = fmaf(E1.y * t, __fdividef(1.f, x), a1);
                }
            }
            {
                float x = jf - E2.x;
                if (fabsf(x) < 40.f) {
                    float t = fmaf(cjs, E2.z, onej);
                    t = fmaf(sjs, E2.w, t);
                    a2v = fmaf(E2.y * t, __fdividef(1.f, x), a2v);
                }
            }
            {
                float x = jf - E3.x;
                if (fabsf(x) < 40.f) {
                    float t = fmaf(cjs, E3.z, onej);
                    t = fmaf(sjs, E3.w, t);
                    a3 = fmaf(E3.y * t, __fdividef(1.f, x), a3);
                }
            }
        }
        for (; e < e_hi; e++) {
            float4 E0 = sEnt[e];
            float x = jf - E0.x;
            if (fabsf(x) < 40.f) {
                float t = fmaf(cjs, E0.z, onej);
                t = fmaf(sjs, E0.w, t);
                a0 = fmaf(E0.y * t, __fdividef(1.f, x), a0);
            }
        }
        float acc = (a0 + a1) + (a2v + a3);

        // wrapped near-field taps land only in bins [3928, 3967]
        if (act && wstart + 31 >= RIR_LENGTH - PAD) {
            for (int w = 0; w < nwr; w++) {
                float4 A = s_wrap[2 * w], B = s_wrap[2 * w + 1];
                float x = (jf - A.x) + A.y;       // exact: int diff + frac
                if (fabsf(x) < 40.f) {
                    float t = fmaf(cjs, B.x, onej);
                    t = fmaf(sjs, B.y, t);
                    acc = fmaf(A.z * t, __fdividef(1.f, x), acc);
                }
            }
        }
        // spikes (rare)
        for (int sp = 0; sp < nsp; sp++)
            if (s_spk_i[sp] == j) acc += s_spk_a[sp];

        if (act) orir[j] = acc;
    }
}

// ---------------------------------------------------------------------------
extern "C" void kernel_launch(void* const* d_in, const int* in_sizes, int n_in,
                              void* d_out, int out_size) {
    const float* inp = (const float*)d_in[0];
    float* out = (float*)d_out;

    const int dynbytes = MAXE * (int)(sizeof(float4) + sizeof(float2));  // 119,808
    cudaFuncSetAttribute(k_all, cudaFuncAttributeMaxDynamicSharedMemorySize, dynbytes);
    k_all<<<BATCH, TPB, dynbytes>>>(inp, out);
}

// round 8
// speedup vs baseline: 2.3092x; 1.5702x over previous
#include <cuda_runtime.h>
#include <math.h>

#define RIR_LENGTH 3968
#define PAD        40
#define BATCH      128
#define MAXO       15
#define GRID_N     31
#define GRID_TOT   29791
#define NIMG       4991          // |x|+|y|+|z| <= 15 lattice points
#define FSR        46.64723032f  // fp32(16000/343)
#define INV_PI     0.3183098862f

#define DIMAX      4007          // di <= 4007 <=> lowest tap bin <= 3967
#define BSH        3             // bucket = 8 delay-bins
#define NBUCK      501           // ceil(4008/8)
#define MAXE       4992
#define WMAX       64
#define SPMAX      32
#define TPB        1024
#define AITER      ((NIMG + TPB - 1) / TPB)   // 5

__device__ int g_xyz[NIMG + 32];
__device__ int g_cnt;

__global__ void k_reset() { if (threadIdx.x == 0) g_cnt = 0; }

__global__ void k_build_xyz() {
    int idx = blockIdx.x * blockDim.x + threadIdx.x;
    if (idx >= GRID_TOT) return;
    int iz  = idx / 961;
    int rem = idx - iz * 961;
    int iy  = rem / 31;
    int ix  = rem - iy * 31;
    ix -= MAXO; iy -= MAXO; iz -= MAXO;
    if (abs(ix) + abs(iy) + abs(iz) <= MAXO) {
        int p = atomicAdd(&g_cnt, 1);
        if (p < NIMG)
            g_xyz[p] = (ix + 16) | ((iy + 16) << 8) | ((iz + 16) << 16);
    }
}

// ---------------------------------------------------------------------------
__global__ __launch_bounds__(TPB) void k_all(const float* __restrict__ inp,
                                             float* __restrict__ out) {
    extern __shared__ __align__(16) char dynsm[];
    float4* sEnt   = (float4*)dynsm;                            // [MAXE]
    float2* sCache = (float2*)(dynsm + MAXE * sizeof(float4));  // [MAXE]

    __shared__ float  sPW[16], sPL[9], sPH[9], sGeo[9];
    __shared__ int    hist[NBUCK], base[NBUCK + 1], cur[NBUCK];
    __shared__ int    segbase[33];
    __shared__ int    s_nsp, s_nwr;
    __shared__ int    s_spk_i[SPMAX];
    __shared__ float  s_spk_a[SPMAX];
    __shared__ float4 s_wrap[WMAX * 2];

    const int b   = blockIdx.x;
    const int tid = threadIdx.x;

    for (int k = tid; k < NBUCK; k += TPB) hist[k] = 0;
    if (tid == 0) {
        s_nsp = 0; s_nwr = 0;
        const float* r = inp + b * 12;
        float rx = r[0], ry = r[1], rz = r[2];
        sGeo[0] = rx;                  sGeo[1] = ry;                  sGeo[2] = rz;
        sGeo[3] = __fmul_rn(r[3], rx); sGeo[4] = __fmul_rn(r[4], ry); sGeo[5] = __fmul_rn(r[5], rz);
        sGeo[6] = __fmul_rn(r[6], rx); sGeo[7] = __fmul_rn(r[7], ry); sGeo[8] = __fmul_rn(r[8], rz);
        float aw  = __fadd_rn(__fmul_rn(r[9],  0.84f), 0.01f);
        float a4  = __fadd_rn(__fmul_rn(r[10], 0.84f), 0.01f);
        float a5  = __fadd_rn(__fmul_rn(r[11], 0.84f), 0.01f);
        double trw = sqrt(1.0 - (double)aw);
        double tr4 = sqrt(1.0 - (double)a4);
        double tr5 = sqrt(1.0 - (double)a5);
        double p = 1.0;
        for (int e = 0; e < 16; e++) { sPW[e] = (float)p; p *= trw; }
        p = 1.0;
        for (int e = 0; e < 9;  e++) { sPL[e] = (float)p; p *= tr4; }
        p = 1.0;
        for (int e = 0; e < 9;  e++) { sPH[e] = (float)p; p *= tr5; }
        // toa
        float dx = __fsub_rn(__fmul_rn(r[3], rx), __fmul_rn(r[6], rx));
        float dy = __fsub_rn(__fmul_rn(r[4], ry), __fmul_rn(r[7], ry));
        float dz = __fsub_rn(__fmul_rn(r[5], rz), __fmul_rn(r[8], rz));
        float ssq = __fadd_rn(__fadd_rn(__fmul_rn(dx, dx), __fmul_rn(dy, dy)),
                              __fmul_rn(dz, dz));
        out[BATCH * RIR_LENGTH + b] =
            __fadd_rn((float)PAD, __fmul_rn(__fsqrt_rn(ssq), FSR));
    }
    __syncthreads();

    const float d0 = sGeo[0], d1 = sGeo[1], d2 = sGeo[2];
    const float m0 = sGeo[3], m1 = sGeo[4], m2 = sGeo[5];
    const float s0 = sGeo[6], s1 = sGeo[7], s2v = sGeo[8];

    // ---- phase A: per-image delay/amp + histogram ----
    #pragma unroll
    for (int it = 0; it < AITER; it++) {
        int i = it * TPB + tid;
        if (i >= NIMG) break;
        int pk = g_xyz[i];
        int ix = (pk & 255) - 16;
        int iy = ((pk >> 8) & 255) - 16;
        int iz = (pk >> 16) - 16;
        float img0 = (ix & 1) ? __fsub_rn(__fmul_rn(d0, (float)(ix + 1)), s0)
                              : __fadd_rn(__fmul_rn(d0, (float)ix), s0);
        float img1 = (iy & 1) ? __fsub_rn(__fmul_rn(d1, (float)(iy + 1)), s1)
                              : __fadd_rn(__fmul_rn(d1, (float)iy), s1);
        float img2 = (iz & 1) ? __fsub_rn(__fmul_rn(d2, (float)(iz + 1)), s2v)
                              : __fadd_rn(__fmul_rn(d2, (float)iz), s2v);
        float e0 = __fsub_rn(img0, m0);
        float e1 = __fsub_rn(img1, m1);
        float e2 = __fsub_rn(img2, m2);
        float ssq = __fadd_rn(__fadd_rn(__fmul_rn(e0, e0), __fmul_rn(e1, e1)),
                              __fmul_rn(e2, e2));
        float dist  = __fsqrt_rn(ssq);
        float delay = __fmul_rn(dist, FSR);
        float dif   = ceilf(delay);
        int   di    = (int)dif;
        float amp   = -1.0f;
        if (di <= DIMAX) {
            int axy  = abs(ix) + abs(iy);
            int elo2 = (iz >= 0) ? (iz >> 1)       : ((-iz + 1) >> 1);
            int ehi2 = (iz >= 0) ? ((iz + 1) >> 1) : ((-iz) >> 1);
            float att = sPW[axy] * sPL[elo2] * sPH[ehi2];
            amp = __fdiv_rn(att, dist);
            if (__fsub_rn(dif, delay) != 0.0f)
                atomicAdd(&hist[di >> BSH], 1);
        }
        sCache[i] = make_float2(delay, amp);
    }
    __syncthreads();

    // ---- two-level prefix scan over NBUCK buckets ----
    if (tid < 32) {
        int s = 0;
        int q0 = tid * 16;
        #pragma unroll
        for (int q = 0; q < 16; q++) {
            int k = q0 + q;
            if (k < NBUCK) s += hist[k];
        }
        int x = s;
        #pragma unroll
        for (int d = 1; d < 32; d <<= 1) {
            int v = __shfl_up_sync(0xffffffffu, x, d);
            if (tid >= d) x += v;
        }
        segbase[tid] = x - s;                  // exclusive
        if (tid == 31) segbase[32] = x;        // total
    }
    __syncthreads();
    for (int k = tid; k < NBUCK; k += TPB) {
        int s = segbase[k >> 4];
        for (int q = k & ~15; q < k; q++) s += hist[q];
        base[k] = s;
        cur[k]  = s;
    }
    if (tid == 0) base[NBUCK] = segbase[32];
    __syncthreads();

    // ---- phase B: finalize entries ----
    #pragma unroll
    for (int it = 0; it < AITER; it++) {
        int c = it * TPB + tid;
        if (c >= NIMG) break;
        float2 E = sCache[c];
        float delay = E.x, amp = E.y;
        if (amp < 0.0f) continue;              // culled (di > DIMAX)
        float dif = ceilf(delay);
        int   di  = (int)dif;
        float frac = __fsub_rn(dif, delay);
        if (frac == 0.0f) {                    // pure spike: sinc peak only
            if (di < RIR_LENGTH) {
                int sp = atomicAdd(&s_nsp, 1);
                if (sp < SPMAX) { s_spk_i[sp] = di; s_spk_a[sp] = amp; }
            }
            continue;
        }
        float a2 = 0.5f * INV_PI * amp * sinpif(frac);
        if (di & 1) a2 = -a2;                  // (-1)^di
        int dm = di % 80;
        float cD, sD;
        sincospif(((float)dm - frac) * 0.025f, &sD, &cD);
        int slot = atomicAdd(&cur[di >> BSH], 1);
        sEnt[slot] = make_float4(delay, a2, cD, sD);
        if (di < PAD) {                        // near-field: JAX wrap duplicate
            int w = atomicAdd(&s_nwr, 1);
            if (w < WMAX) {
                int dm2 = (dm + 48) % 80;      // (di + 3968) % 80
                float cW, sW;
                sincospif(((float)dm2 - frac) * 0.025f, &sW, &cW);
                s_wrap[2 * w + 0] = make_float4((float)(di + RIR_LENGTH), frac, a2, 0.f);
                s_wrap[2 * w + 1] = make_float4(cW, sW, 0.f, 0.f);
            }
        }
    }
    __syncthreads();

    // ---- phase D: branchless gather, 32 consecutive bins per warp ----
    int nsp = min(s_nsp, SPMAX);
    int nwr = min(s_nwr, WMAX);
    float* orir = out + b * RIR_LENGTH;

    #pragma unroll
    for (int m = 0; m < 4; m++) {
        int j      = m * TPB + tid;
        int wstart = m * TPB + (tid & ~31);
        bool act   = (j < RIR_LENGTH);         // warp-uniform (3968 % 32 == 0)

        float jf = (float)j;
        int jm = j % 80;
        float cj, sj;
        sincospif((float)jm * 0.025f, &sj, &cj);
        float onej = (jm & 1) ? -1.f : 1.f;
        float cjs = onej * cj;
        float sjs = onej * sj;

        int lob = (wstart - 39) >> BSH; if (lob < 0) lob = 0;
        int hib = (wstart + 71) >> BSH; if (hib > NBUCK - 1) hib = NBUCK - 1;
        int e_lo = base[lob];
        int e_hi = act ? base[hib + 1] : e_lo;

        float a0 = 0.f, a1 = 0.f, a2v = 0.f, a3 = 0.f;
        int e = e_lo;
        for (; e + 4 <= e_hi; e += 4) {
            float4 E0 = sEnt[e], E1 = sEnt[e + 1], E2 = sEnt[e + 2], E3 = sEnt[e + 3];
            {
                float x = jf - E0.x;
                float t = fmaf(cjs, E0.z, onej);
                t = fmaf(sjs, E0.w, t);
                t = (fabsf(x) < 40.f) ? t : 0.f;
                a0 = fmaf(E0.y * t, __fdividef(1.f, x), a0);
            }
            {
                float x = jf - E1.x;
                float t = fmaf(cjs, E1.z, onej);
                t = fmaf(sjs, E1.w, t);
                t = (fabsf(x) < 40.f) ? t : 0.f;
                a1 = fmaf(E1.y * t, __fdividef(1.f, x), a1);
            }
            {
                float x = jf - E2.x;
                float t = fmaf(cjs, E2.z, onej);
                t = fmaf(sjs, E2.w, t);
                t = (fabsf(x) < 40.f) ? t : 0.f;
                a2v = fmaf(E2.y * t, __fdividef(1.f, x), a2v);
            }
            {
                float x = jf - E3.x;
                float t = fmaf(cjs, E3.z, onej);
                t = fmaf(sjs, E3.w, t);
                t = (fabsf(x) < 40.f) ? t : 0.f;
                a3 = fmaf(E3.y * t, __fdividef(1.f, x), a3);
            }
        }
        for (; e < e_hi; e++) {
            float4 E0 = sEnt[e];
            float x = jf - E0.x;
            float t = fmaf(cjs, E0.z, onej);
            t = fmaf(sjs, E0.w, t);
            t = (fabsf(x) < 40.f) ? t : 0.f;
            a0 = fmaf(E0.y * t, __fdividef(1.f, x), a0);
        }
        float acc = (a0 + a1) + (a2v + a3);

        // wrapped near-field taps land only in bins [3928, 3967]
        if (act && wstart + 31 >= RIR_LENGTH - PAD) {
            for (int w = 0; w < nwr; w++) {
                float4 A = s_wrap[2 * w], B = s_wrap[2 * w + 1];
                float x = (jf - A.x) + A.y;    // exact: int diff + frac
                float t = fmaf(cjs, B.x, onej);
                t = fmaf(sjs, B.y, t);
                t = (fabsf(x) < 40.f) ? t : 0.f;
                acc = fmaf(A.z * t, __fdividef(1.f, x), acc);
            }
        }
        // spikes (rare)
        for (int sp = 0; sp < nsp; sp++)
            if (s_spk_i[sp] == j) acc += s_spk_a[sp];

        if (act) orir[j] = acc;
    }
}

// ---------------------------------------------------------------------------
extern "C" void kernel_launch(void* const* d_in, const int* in_sizes, int n_in,
                              void* d_out, int out_size) {
    const float* inp = (const float*)d_in[0];
    float* out = (float*)d_out;

    const int dynbytes = MAXE * (int)(sizeof(float4) + sizeof(float2));  // 119,808
    cudaFuncSetAttribute(k_all, cudaFuncAttributeMaxDynamicSharedMemorySize, dynbytes);
    k_reset<<<1, 32>>>();
    k_build_xyz<<<(GRID_TOT + 255) / 256, 256>>>();
    k_all<<<BATCH, TPB, dynbytes>>>(inp, out);
}